// round 1
// baseline (speedup 1.0000x reference)
#include <cuda_runtime.h>
#include <cuda_bf16.h>
#include <math.h>

// Problem constants (from reference: B, N, M, C, S = 4, 16384, 128, 128, 512)
#define BB    4
#define NPTS  16384
#define MBOX  128
#define CFEAT 128
#define SSAMP 512
#define ROWW  (3 + CFEAT)          // 131 floats per pooled row
#define NTHREADS 512
#define NWARPS   (NTHREADS / 32)

__global__ __launch_bounds__(NTHREADS, 2)
void roipool3d_kernel(const float* __restrict__ points,   // (B, N, 3)
                      const float* __restrict__ feats,    // (B, N, C)
                      const float* __restrict__ boxes,    // (B, M, 7)
                      float* __restrict__ out,            // pooled (B,M,S,131) then flags (B,M)
                      long long flag_off)
{
    const int bm = blockIdx.x;            // 0 .. B*M-1
    const int b  = bm / MBOX;

    // --- Box parameters (all threads read; L1/L2 cached) ---
    const float* box = boxes + (size_t)bm * 7;
    const float cx = box[0];
    const float cy = box[1];
    const float dz = box[5];
    const float cz = box[2] + 0.5f * dz;   // bottom center -> geometric center
    const float dx = box[3];
    const float dy = box[4];
    const float rz = box[6];
    const float cosa = cosf(-rz);
    const float sina = sinf(-rz);
    const float hx = 0.5f * dx;
    const float hy = 0.5f * dy;
    const float hz = 0.5f * dz;

    __shared__ int   s_list[SSAMP];        // ordered in-box point indices (first S)
    __shared__ int   s_wcnt[NWARPS];
    __shared__ int   s_base;               // running in-box count

    const int tid  = threadIdx.x;
    const int wid  = tid >> 5;
    const int lane = tid & 31;

    if (tid == 0) s_base = 0;
    __syncthreads();

    const float* pts = points + (size_t)b * NPTS * 3;

    // --- Phase 1: ordered stream compaction of in-box point indices ---
    #pragma unroll 1
    for (int start = 0; start < NPTS; start += NTHREADS) {
        const int i = start + tid;
        const float px = pts[i * 3 + 0];
        const float py = pts[i * 3 + 1];
        const float pz = pts[i * 3 + 2];

        const float sx = px - cx;
        const float sy = py - cy;
        const float lx = sx * cosa - sy * sina;
        const float ly = sx * sina + sy * cosa;

        const bool in =
            (fabsf(pz - cz) <= hz) &&
            (lx > -hx) && (lx < hx) &&
            (ly > -hy) && (ly < hy);

        const unsigned ball = __ballot_sync(0xffffffffu, in);
        if (lane == 0) s_wcnt[wid] = __popc(ball);
        __syncthreads();

        int wpre = 0;
        #pragma unroll
        for (int w = 0; w < NWARPS; w++)
            wpre += (w < wid) ? s_wcnt[w] : 0;

        const int pos = s_base + wpre + __popc(ball & ((1u << lane) - 1u));
        if (in && pos < SSAMP) s_list[pos] = i;
        __syncthreads();

        if (tid == 0) {
            int tot = 0;
            #pragma unroll
            for (int w = 0; w < NWARPS; w++) tot += s_wcnt[w];
            s_base += tot;
        }
        __syncthreads();

        if (s_base >= SSAMP) break;   // cnt >= S: wrap index j % cnt == j, list full
    }

    const int cnt = s_base;

    // --- Phase 2: emit pooled rows ---
    float* o = out + (size_t)bm * SSAMP * ROWW;

    if (cnt == 0) {
        for (int i = tid; i < SSAMP * ROWW; i += NTHREADS)
            o[i] = 0.0f;
    } else {
        // one warp per row; 32-lane coalesced stores across the 131-float row
        for (int s = wid; s < SSAMP; s += NWARPS) {
            const int j   = (cnt >= SSAMP) ? s : (s % cnt);
            const int src = s_list[j];
            const float* p = pts + (size_t)src * 3;
            const float* f = feats + ((size_t)b * NPTS + src) * CFEAT;
            float* row = o + (size_t)s * ROWW;
            #pragma unroll
            for (int e = lane; e < ROWW; e += 32)
                row[e] = (e < 3) ? p[e] : f[e - 3];
        }
    }

    // --- Empty flag (int32 0/1 in reference -> value-cast to float output) ---
    if (tid == 0)
        out[flag_off + bm] = (cnt == 0) ? 1.0f : 0.0f;
}

extern "C" void kernel_launch(void* const* d_in, const int* in_sizes, int n_in,
                              void* d_out, int out_size)
{
    const float* points = (const float*)d_in[0];   // (B, N, 3)
    const float* feats  = (const float*)d_in[1];   // (B, N, C)
    const float* boxes  = (const float*)d_in[2];   // (B, M, 7)
    float* out = (float*)d_out;

    // flags live in the tail of the output buffer
    const long long flag_off = (long long)out_size - (long long)BB * MBOX;

    roipool3d_kernel<<<BB * MBOX, NTHREADS>>>(points, feats, boxes, out, flag_off);
}

// round 3
// speedup vs baseline: 1.6649x; 1.6649x over previous
#include <cuda_runtime.h>
#include <cuda_bf16.h>
#include <math.h>

// Problem constants (B, N, M, C, S = 4, 16384, 128, 128, 512)
#define BB    4
#define NPTS  16384
#define MBOX  128
#define CFEAT 128
#define SSAMP 512
#define ROWW  (3 + CFEAT)            // 131 floats per pooled row
#define NTHREADS 256
#define NWARPS   (NTHREADS / 32)     // 8
#define SEG      (NPTS / NWARPS)     // 2048 points per warp segment
#define ITERS    (SEG / 32)          // 64 warp iterations

__global__ __launch_bounds__(NTHREADS)
void roipool3d_kernel(const float* __restrict__ points,   // (B, N, 3)
                      const float* __restrict__ feats,    // (B, N, C)
                      const float* __restrict__ boxes,    // (B, M, 7)
                      float* __restrict__ out,            // pooled (B,M,S,131) then flags (B,M)
                      long long flag_off)
{
    const int bm = blockIdx.x;            // 0 .. B*M-1
    const int b  = bm >> 7;               // bm / MBOX

    // --- Box parameters ---
    const float* box = boxes + (size_t)bm * 7;
    const float cx = box[0];
    const float cy = box[1];
    const float dz = box[5];
    const float cz = box[2] + 0.5f * dz;   // bottom center -> geometric center
    const float dx = box[3];
    const float dy = box[4];
    const float rz = box[6];
    const float cosa = cosf(-rz);
    const float sina = sinf(-rz);
    const float hx = 0.5f * dx;
    const float hy = 0.5f * dy;
    const float hz = 0.5f * dz;

    // Per-warp compaction buffers: contiguous segments => warp-order concat
    // reproduces global point-index order exactly.
    __shared__ int s_buf[NWARPS][SSAMP];   // 16 KB
    __shared__ int s_cnt[NWARPS];
    __shared__ int s_list[SSAMP];          // 2 KB

    const int tid  = threadIdx.x;
    const int wid  = tid >> 5;
    const int lane = tid & 31;
    const unsigned lmask_lt = (1u << lane) - 1u;

    const float* pts = points + (size_t)b * NPTS * 3;

    // --- Phase 1: warp-autonomous ordered compaction (no block barriers) ---
    {
        const int seg_start = wid * SEG;
        int wcnt = 0;

        #pragma unroll 4
        for (int it = 0; it < ITERS; ++it) {
            if (wcnt >= SSAMP) break;      // local rank >= S can never be used

            const int i = seg_start + it * 32 + lane;
            const float px = pts[i * 3 + 0];
            const float py = pts[i * 3 + 1];
            const float pz = pts[i * 3 + 2];

            const float sx = px - cx;
            const float sy = py - cy;
            const float lx = sx * cosa - sy * sina;
            const float ly = sx * sina + sy * cosa;

            const bool in =
                (fabsf(pz - cz) <= hz) &&
                (fabsf(lx) < hx) &&
                (fabsf(ly) < hy);

            const unsigned ball = __ballot_sync(0xffffffffu, in);
            const int r = wcnt + __popc(ball & lmask_lt);
            if (in && r < SSAMP) s_buf[wid][r] = i;
            wcnt += __popc(ball);
        }
        if (lane == 0) s_cnt[wid] = wcnt;
    }
    __syncthreads();

    // --- Merge: tiny 8-entry prefix, each warp copies its own buffer ---
    int total = 0;
    int off   = 0;
    #pragma unroll
    for (int w = 0; w < NWARPS; ++w) {
        const int c = s_cnt[w];
        off   += (w < wid) ? c : 0;
        total += c;
    }
    {
        const int stored = min(s_cnt[wid], SSAMP);
        for (int k = lane; k < stored; k += 32) {
            const int g = off + k;
            if (g < SSAMP) s_list[g] = s_buf[wid][k];
        }
    }
    __syncthreads();

    const int cnt = total;   // true count (or >=S if a warp early-broke; only >=S matters)

    // --- Phase 2: emit pooled rows (one warp per row, streaming stores) ---
    float* o = out + (size_t)bm * SSAMP * ROWW;

    if (cnt == 0) {
        for (int i = tid; i < SSAMP * ROWW; i += NTHREADS)
            __stcs(o + i, 0.0f);
    } else {
        for (int s = wid; s < SSAMP; s += NWARPS) {
            const int j   = (cnt >= SSAMP) ? s : (s % cnt);
            const int src = s_list[j];
            const float* p = pts + (size_t)src * 3;
            const float* f = feats + ((size_t)b * NPTS + src) * CFEAT;
            float* row = o + (size_t)s * ROWW;

            if (lane < 3) __stcs(row + lane, p[lane]);
            #pragma unroll
            for (int e = lane; e < CFEAT; e += 32)
                __stcs(row + 3 + e, f[e]);
        }
    }

    // --- Empty flag (reference int32 0/1, value-cast to float output) ---
    if (tid == 0)
        out[flag_off + bm] = (cnt == 0) ? 1.0f : 0.0f;
}

extern "C" void kernel_launch(void* const* d_in, const int* in_sizes, int n_in,
                              void* d_out, int out_size)
{
    const float* points = (const float*)d_in[0];   // (B, N, 3)
    const float* feats  = (const float*)d_in[1];   // (B, N, C)
    const float* boxes  = (const float*)d_in[2];   // (B, M, 7)
    float* out = (float*)d_out;

    const long long flag_off = (long long)out_size - (long long)BB * MBOX;

    roipool3d_kernel<<<BB * MBOX, NTHREADS>>>(points, feats, boxes, out, flag_off);
}